// round 8
// baseline (speedup 1.0000x reference)
#include <cuda_runtime.h>
#include <cuda_fp16.h>

#define B_ 512
#define S_ 168
#define F_ 12
#define H_ 128
#define O_ 3
#define S2_ (S_ * S_)
#define ROWS 8

typedef unsigned int u32;

// ---------------- device scratch ----------------
__device__ uint4 g_W0f[16 * 9 * 32];    // L0 fragments [tile][kstep][lane]  (K=144: x|pad|h)
__device__ uint4 g_W1f[16 * 16 * 32];   // L1 fragments
__device__ uint4 g_Hf[24 * 16 * 32];    // head fragments (re-ordered blocks)
__device__ float g_bh[384];             // merged head bias (re-ordered)
__device__ float g_T[3 * S2_];          // transposed [L][si][so]
__device__ float g_WfT[3 * S2_];        // transposed [c][s][p]
__device__ float g_mean[B_ * F_];
__device__ float g_x1[B_ * S_ * F_];
__device__ float g_x2[B_ * S_ * O_];
__device__ float g_x3[B_ * S_ * O_];
__device__ float g_hs[B_ * S_ * H_];

// ---------------- helpers ----------------
__device__ __forceinline__ float siluf(float x) { return __fdividef(x, 1.f + __expf(-x)); }
__device__ __forceinline__ float sigf(float x)  { return __fdividef(1.f, 1.f + __expf(-x)); }
__device__ __forceinline__ float tanhf_fast(float x) {
    float e = __expf(2.f * x);
    return 1.f - __fdividef(2.f, e + 1.f);
}
__device__ __forceinline__ u32 hpack(float a, float b) {
    __half2 h = __floats2half2_rn(a, b);
    return *reinterpret_cast<u32*>(&h);
}
__device__ __forceinline__ void mma16816(float* d, uint4 A, u32 b0, u32 b1) {
    asm volatile(
        "mma.sync.aligned.m16n8k16.row.col.f32.f16.f16.f32 "
        "{%0,%1,%2,%3},{%4,%5,%6,%7},{%8,%9},{%0,%1,%2,%3};"
        : "+f"(d[0]), "+f"(d[1]), "+f"(d[2]), "+f"(d[3])
        : "r"(A.x), "r"(A.y), "r"(A.z), "r"(A.w), "r"(b0), "r"(b1));
}
#define CLUSTER_SYNC() do { \
    asm volatile("barrier.cluster.arrive.aligned;" ::: "memory"); \
    asm volatile("barrier.cluster.wait.aligned;" ::: "memory"); } while (0)

__device__ __forceinline__ void sts_r16(u32 a, __half v) {
    asm volatile("st.shared::cluster.b16 [%0], %1;" :: "r"(a), "h"(__half_as_ushort(v)));
}
__device__ __forceinline__ void mbar_init(u32 a, u32 cnt) {
    asm volatile("mbarrier.init.shared.b64 [%0], %1;" :: "r"(a), "r"(cnt) : "memory");
}
__device__ __forceinline__ void mbar_arrive_remote(u32 a) {
    asm volatile("mbarrier.arrive.release.cluster.shared::cluster.b64 _, [%0];" :: "r"(a) : "memory");
}
__device__ __forceinline__ void mbar_wait(u32 a, u32 parity) {
    asm volatile(
        "{\n\t.reg .pred P;\n"
        "W%=:\n\t"
        "mbarrier.try_wait.parity.acquire.cluster.shared::cta.b64 P, [%0], %1, 0x989680;\n\t"
        "@P bra D%=;\n\t"
        "bra W%=;\n"
        "D%=:\n\t}"
        :: "r"(a), "r"(parity) : "memory");
}

// weight element accessors
// L0 K layout: k in [0,12) -> x, [12,16) -> zero pad, [16,144) -> h[k-16]
__device__ __forceinline__ float w0_at(const float* W, int o, int k) {
    if (k < 12)  return W[o * 140 + k];
    if (k < 16)  return 0.f;
    return W[o * 140 + (k - 4)];     // 12 + (k-16)
}
// head ordering: block r (192 rows) = [ff1(64r:64r+64); ff2(64r:64r+64); gate(64r:64r+64)]
__device__ __forceinline__ float wh_at(const float* f1, const float* f2,
                                       const float* ta, const float* tb, int m, int k) {
    int blk = m / 192, o = m % 192, base = blk * 64;
    if (o < 64)  return f1[(base + o) * 256 + k];
    if (o < 128) return f2[(base + o - 64) * 256 + k];
    return ta[(base + o - 128) * 256 + k] + tb[(base + o - 128) * 256 + k];
}

// ---------------- fragment precompute ----------------
__global__ void k_prep(const float* __restrict__ Wb0, const float* __restrict__ Wb1,
                       const float* __restrict__ Wff1, const float* __restrict__ Wff2,
                       const float* __restrict__ Wta, const float* __restrict__ Wtb,
                       const float* __restrict__ bff1, const float* __restrict__ bff2,
                       const float* __restrict__ bta, const float* __restrict__ btb) {
    int idx = blockIdx.x * blockDim.x + threadIdx.x;
    const int N0 = 16 * 9 * 32, N1 = 16 * 16 * 32, NH = 24 * 16 * 32;
    if (idx < N0 + N1 + NH) {
        int which, tile, ks, l, i = idx;
        if (i < N0)           { which = 0; tile = i / (9 * 32);  ks = (i / 32) % 9; }
        else if (i < N0 + N1) { which = 1; i -= N0; tile = i / (16 * 32); ks = (i / 32) % 16; }
        else                  { which = 2; i -= N0 + N1; tile = i / (16 * 32); ks = (i / 32) % 16; }
        l = i % 32;
        int g = l / 4, ti = l % 4;
        int r0 = tile * 16 + g, k0 = ks * 16 + ti * 2;
        float e[4][2];
        for (int half = 0; half < 2; half++) {
            for (int rr = 0; rr < 2; rr++) {
                for (int cc = 0; cc < 2; cc++) {
                    int o = r0 + rr * 8, k = k0 + half * 8 + cc;
                    float wv;
                    if (which == 0)      wv = w0_at(Wb0, o, k);
                    else if (which == 1) wv = Wb1[o * 256 + k];
                    else                 wv = wh_at(Wff1, Wff2, Wta, Wtb, o, k);
                    e[half * 2 + rr][cc] = wv;
                }
            }
        }
        uint4 out;
        out.x = hpack(e[0][0], e[0][1]);
        out.y = hpack(e[1][0], e[1][1]);
        out.z = hpack(e[2][0], e[2][1]);
        out.w = hpack(e[3][0], e[3][1]);
        if (which == 0)      g_W0f[idx] = out;
        else if (which == 1) g_W1f[idx - N0] = out;
        else                 g_Hf[idx - N0 - N1] = out;
    } else if (idx < N0 + N1 + NH + 384) {
        int m = idx - N0 - N1 - NH;
        int blk = m / 192, o = m % 192, base = blk * 64;
        float b;
        if (o < 64)       b = bff1[base + o];
        else if (o < 128) b = bff2[base + o - 64];
        else              b = bta[base + o - 128] + btb[base + o - 128];
        g_bh[m] = b;
    }
}

// ---------------- collapsed _sff operators (transposed) ----------------
__device__ __forceinline__ float sff_contrib(const float* __restrict__ conv,
                                             const float* __restrict__ lin,
                                             int p, int seg, int pad, int so, int si) {
    int phase = so % p, q = so / p;
    float acc = 0.f;
    for (int kk = 0; kk < seg; ++kk) {
        int d = si - (kk * p + phase);
        float c = 0.f;
        if (d >= -pad && d <= pad) c = conv[d + pad];
        if (d == 0) c += 1.f;
        acc += lin[q * seg + kk] * c;
    }
    return acc;
}

__global__ void k_build_T(const float* __restrict__ c3, const float* __restrict__ l3,
                          const float* __restrict__ c6, const float* __restrict__ l6,
                          const float* __restrict__ c12, const float* __restrict__ l12,
                          const float* __restrict__ c24, const float* __restrict__ l24) {
    int idx = blockIdx.x * blockDim.x + threadIdx.x;
    if (idx >= 3 * S2_) return;
    int L = idx / S2_, r = idx % S2_;
    int so = r / S_, si = r % S_;
    float a = sff_contrib(c3 + L * 3, l3 + L * 56 * 56, 3, 56, 1, so, si)
            + sff_contrib(c6 + L * 7, l6 + L * 28 * 28, 6, 28, 3, so, si)
            + sff_contrib(c12 + L * 13, l12 + L * 14 * 14, 12, 14, 6, so, si)
            + sff_contrib(c24 + L * 25, l24 + L * 7 * 7, 24, 7, 12, so, si);
    g_T[L * S2_ + si * S_ + so] = 0.25f * a;
}

__global__ void k_twf(const float* __restrict__ Wfits) {
    int idx = blockIdx.x * blockDim.x + threadIdx.x;
    if (idx >= 3 * S2_) return;
    int c = idx / S2_, r = idx % S2_;
    int s = r / S_, p = r % S_;
    g_WfT[c * S2_ + s * S_ + p] = Wfits[c * S2_ + p * S_ + s];
}

__global__ void k_mean(const float* __restrict__ x) {
    int w = (blockIdx.x * blockDim.x + threadIdx.x) >> 5;
    int lane = threadIdx.x & 31;
    if (w >= B_ * F_) return;
    const float* p = x + w * S_;
    float s = 0.f;
    for (int i = lane; i < S_; i += 32) s += p[i];
#pragma unroll
    for (int o = 16; o; o >>= 1) s += __shfl_xor_sync(0xffffffffu, s, o);
    if (!lane) g_mean[w] = s * (1.f / (float)S_);
}

// ---------------- fused front ----------------
__global__ void k_front(const float* __restrict__ x) {
    __shared__ float xs[S_][F_];
    __shared__ float x1s[S_][4];
    int b = blockIdx.x, t = threadIdx.x;
    for (int i = t; i < S_ * F_; i += blockDim.x) {
        int si = i / F_, f = i % F_;
        xs[si][f] = x[b * F_ * S_ + f * S_ + si] - g_mean[b * F_ + f];
    }
    __syncthreads();
    if (t < S_) {
        float acc[F_];
#pragma unroll
        for (int f = 0; f < F_; f++) acc[f] = 0.f;
        for (int si = 0; si < S_; ++si) {
            float tw = g_T[si * S_ + t];
#pragma unroll
            for (int f = 0; f < F_; f++) acc[f] = fmaf(tw, xs[si][f], acc[f]);
        }
        float* o = g_x1 + (b * S_ + t) * F_;
#pragma unroll
        for (int f = 0; f < F_; f++) o[f] = acc[f];
        x1s[t][0] = acc[0]; x1s[t][1] = acc[1]; x1s[t][2] = acc[2];
    }
    __syncthreads();
    if (t < S_) {
        float a2[3] = {0.f, 0.f, 0.f}, a3[3] = {0.f, 0.f, 0.f};
        for (int si = 0; si < S_; ++si) {
            float t1 = g_T[S2_ + si * S_ + t];
            float t2 = g_T[2 * S2_ + si * S_ + t];
#pragma unroll
            for (int c = 0; c < 3; c++) {
                a2[c] = fmaf(t1, x1s[si][c], a2[c]);
                a3[c] = fmaf(t2, x1s[si][c], a3[c]);
            }
        }
#pragma unroll
        for (int c = 0; c < 3; c++) {
            g_x2[(b * S_ + t) * 3 + c] = a2[c];
            g_x3[(b * S_ + t) * 3 + c] = a3[c];
        }
    }
}

// ---------------- CfC recurrence: cluster-2 + mbarrier handshakes ----------
// SMEM layout (bytes):
//   [0, 36864)        sW0   (8 tiles x 9 ks x 32 x uint4)
//   [36864, 102400)   sW1   (8 x 16 x 32)
//   [102400, 200704)  sHf   (12 x 16 x 32)
//   [200704, 203392)  in0   8 rows x 168 halfs  ([x12|pad4|h128] used)
//   [203392, 207616)  za    8 x 264 halfs
//   [207616, 211840)  zb    8 x 264 halfs
//   [211840, 218240)  hdro  8 x 200 floats
//   [218240, 219264)  sb0
//   [219264, 220288)  sb1
//   [220288, 221824)  sbh
//   [221824, 221848)  mbarriers: H_h, H_za, H_zb
__global__ void __launch_bounds__(256, 1) __cluster_dims__(2, 1, 1)
k_rnn(const float* __restrict__ bb0, const float* __restrict__ bb1) {
    extern __shared__ __align__(16) char s[];
    uint4*  sW0  = (uint4*)(s);
    uint4*  sW1  = (uint4*)(s + 36864);
    uint4*  sHf  = (uint4*)(s + 102400);
    __half* in0  = (__half*)(s + 200704);
    __half* za   = (__half*)(s + 203392);
    __half* zb   = (__half*)(s + 207616);
    float*  hdro = (float*)(s + 211840);
    float*  sb0  = (float*)(s + 218240);
    float*  sb1  = (float*)(s + 219264);
    float*  sbh  = (float*)(s + 220288);

    const int t = threadIdx.x, w = t >> 5, l = t & 31, g = l >> 2, ti = l & 3;
    u32 rank;
    asm("mov.u32 %0, %%cluster_ctarank;" : "=r"(rank));
    const u32 peer = rank ^ 1u;
    const int bb = (blockIdx.x >> 1) * ROWS;

    u32 base;
    asm("{ .reg .u64 a; cvta.to.shared.u64 a, %1; cvt.u32.u64 %0, a; }" : "=r"(base) : "l"(s));
    u32 in0_l = base + 200704, za_l = base + 203392, zb_l = base + 207616;
    u32 mb_h = base + 221824, mb_za = base + 221832, mb_zb = base + 221840;
    u32 in0_r, za_r, zb_r, mb_h_r, mb_za_r, mb_zb_r;
    asm("mapa.shared::cluster.u32 %0, %1, %2;" : "=r"(in0_r) : "r"(in0_l), "r"(peer));
    asm("mapa.shared::cluster.u32 %0, %1, %2;" : "=r"(za_r) : "r"(za_l), "r"(peer));
    asm("mapa.shared::cluster.u32 %0, %1, %2;" : "=r"(zb_r) : "r"(zb_l), "r"(peer));
    asm("mapa.shared::cluster.u32 %0, %1, %2;" : "=r"(mb_h_r) : "r"(mb_h), "r"(peer));
    asm("mapa.shared::cluster.u32 %0, %1, %2;" : "=r"(mb_za_r) : "r"(mb_za), "r"(peer));
    asm("mapa.shared::cluster.u32 %0, %1, %2;" : "=r"(mb_zb_r) : "r"(mb_zb), "r"(peer));

    // stage this CTA's half of each weight matrix + biases
    {
        const uint4* p0 = g_W0f + rank * 2304;
        for (int i = t; i < 2304; i += 256) sW0[i] = p0[i];
        const uint4* p1 = g_W1f + rank * 4096;
        for (int i = t; i < 4096; i += 256) sW1[i] = p1[i];
        const uint4* ph = g_Hf + rank * 6144;
        for (int i = t; i < 6144; i += 256) sHf[i] = ph[i];
    }
    sb0[t] = bb0[t];
    sb1[t] = bb1[t];
    for (int i = t; i < 384; i += 256) sbh[i] = g_bh[i];
    for (int i = t; i < ROWS * 168; i += 256) in0[i] = __float2half(0.f);
    if (t == 0) {
        mbar_init(mb_h, 256);
        mbar_init(mb_za, 256);
        mbar_init(mb_zb, 256);
    }
    __syncthreads();
    CLUSTER_SYNC();                 // barriers + zeroed buffers visible cluster-wide
    mbar_arrive_remote(mb_h_r);     // pre-fill phase 0 of peer's h barrier (h=0 ready)
    // load x(0)
    for (int i = t; i < ROWS * F_; i += 256) {
        int r = i / F_, f = i % F_;
        in0[r * 168 + f] = __float2half(g_x1[(bb + r) * S_ * F_ + f]);
    }

    const int ra2 = 2 * ti, rb2 = 2 * ti + 1;
    const int hb = 192 * (int)rank;
    const int gob = (8 * (int)rank + w) * 16;   // L0/L1 global out base

    for (int step = 0; step < S_; ++step) {
        const u32 par = step & 1u;
        __syncthreads();   // local: combine(s-1)/prologue writes to in0 visible

        // ================= L0 (K=144: ks0=x, own h ks, peer h ks) ==========
        {
            float dA[4], dB[4];
            dA[0] = dA[1] = sb0[gob + g];
            dA[2] = dA[3] = sb0[gob + g + 8];
            dB[0] = dB[1] = dB[2] = dB[3] = 0.f;
            // ks0: x (local)
            {
                u32 b0 = *(const u32*)&in0[g * 168 + ti * 2];
                u32 b1 = *(const u32*)&in0[g * 168 + ti * 2 + 8];
                mma16816(dA, sW0[(w * 9 + 0) * 32 + l], b0, b1);
            }
            // own h half: ks = 1+4*rank .. 4+4*rank
            int ko = 1 + 4 * (int)rank, kp = 1 + 4 * (int)peer;
#pragma unroll
            for (int j = 0; j < 4; j++) {
                int ks = ko + j;
                u32 b0 = *(const u32*)&in0[g * 168 + ks * 16 + ti * 2];
                u32 b1 = *(const u32*)&in0[g * 168 + ks * 16 + ti * 2 + 8];
                mma16816((j & 1) ? dB : dA, sW0[(w * 9 + ks) * 32 + l], b0, b1);
            }
            mbar_wait(mb_h, par);   // peer h half ready
#pragma unroll
            for (int j = 0; j < 4; j++) {
                int ks = kp + j;
                u32 b0 = *(const u32*)&in0[g * 168 + ks * 16 + ti * 2];
                u32 b1 = *(const u32*)&in0[g * 168 + ks * 16 + ti * 2 + 8];
                mma16816((j & 1) ? dA : dB, sW0[(w * 9 + ks) * 32 + l], b0, b1);
            }
            float v0 = siluf(dA[0] + dB[0]), v1 = siluf(dA[1] + dB[1]);
            float v2 = siluf(dA[2] + dB[2]), v3 = siluf(dA[3] + dB[3]);
            __half h0 = __float2half(v0), h1 = __float2half(v1);
            __half h2 = __float2half(v2), h3 = __float2half(v3);
            int i0 = ra2 * 264 + gob + g, i1 = rb2 * 264 + gob + g;
            za[i0] = h0;     za[i1] = h1;
            za[i0 + 8] = h2; za[i1 + 8] = h3;
            sts_r16(za_r + i0 * 2, h0);       sts_r16(za_r + i1 * 2, h1);
            sts_r16(za_r + (i0 + 8) * 2, h2); sts_r16(za_r + (i1 + 8) * 2, h3);
            mbar_arrive_remote(mb_za_r);
        }
        __syncthreads();   // local za half visible

        // ================= L1 (K=256: own za ks then peer za ks) ==========
        {
            float dA[4], dB[4];
            dA[0] = dA[1] = sb1[gob + g];
            dA[2] = dA[3] = sb1[gob + g + 8];
            dB[0] = dB[1] = dB[2] = dB[3] = 0.f;
            int ko = 8 * (int)rank, kp = 8 * (int)peer;
#pragma unroll
            for (int j = 0; j < 8; j++) {
                int ks = ko + j;
                u32 b0 = *(const u32*)&za[g * 264 + ks * 16 + ti * 2];
                u32 b1 = *(const u32*)&za[g * 264 + ks * 16 + ti * 2 + 8];
                mma16816((j & 1) ? dB : dA, sW1[(w * 16 + ks) * 32 + l], b0, b1);
            }
            mbar_wait(mb_za, par);
#pragma unroll
            for (int j = 0; j < 8; j++) {
                int ks = kp + j;
                u32 b0 = *(const u32*)&za[g * 264 + ks * 16 + ti * 2];
                u32 b1 = *(const u32*)&za[g * 264 + ks * 16 + ti * 2 + 8];
                mma16816((j & 1) ? dA : dB, sW1[(w * 16 + ks) * 32 + l], b0, b1);
            }
            float v0 = siluf(dA[0] + dB[0]), v1 = siluf(dA[1] + dB[1]);
            float v2 = siluf(dA[2] + dB[2]), v3 = siluf(dA[3] + dB[3]);
            __half h0 = __float2half(v0), h1 = __float2half(v1);
            __half h2 = __float2half(v2), h3 = __float2half(v3);
            int i0 = ra2 * 264 + gob + g, i1 = rb2 * 264 + gob + g;
            zb[i0] = h0;     zb[i1] = h1;
            zb[i0 + 8] = h2; zb[i1 + 8] = h3;
            sts_r16(zb_r + i0 * 2, h0);       sts_r16(zb_r + i1 * 2, h1);
            sts_r16(zb_r + (i0 + 8) * 2, h2); sts_r16(zb_r + (i1 + 8) * 2, h3);
            mbar_arrive_remote(mb_zb_r);
        }
        __syncthreads();   // local zb half visible

        // ================= head (this CTA's 192 outs) =====================
        {
            int ko = 8 * (int)rank, kp = 8 * (int)peer;
            if (w < 4) {
                int lt0 = w, lt1 = 8 + w;
                float e0[4], e1[4];
                e0[0] = e0[1] = sbh[hb + lt0 * 16 + g];
                e0[2] = e0[3] = sbh[hb + lt0 * 16 + g + 8];
                e1[0] = e1[1] = sbh[hb + lt1 * 16 + g];
                e1[2] = e1[3] = sbh[hb + lt1 * 16 + g + 8];
#pragma unroll
                for (int j = 0; j < 8; j++) {
                    int ks = ko + j;
                    u32 b0 = *(const u32*)&zb[g * 264 + ks * 16 + ti * 2];
                    u32 b1 = *(const u32*)&zb[g * 264 + ks * 16 + ti * 2 + 8];
                    mma16816(e0, sHf[(lt0 * 16 + ks) * 32 + l], b0, b1);
                    mma16816(e1, sHf[(lt1 * 16 + ks) * 32 + l], b0, b1);
                }
                mbar_wait(mb_zb, par);
#pragma unroll
                for (int j = 0; j < 8; j++) {
                    int ks = kp + j;
                    u32 b0 = *(const u32*)&zb[g * 264 + ks * 16 + ti * 2];
                    u32 b1 = *(const u32*)&zb[g * 264 + ks * 16 + ti * 2 + 8];
                    mma16816(e0, sHf[(lt0 * 16 + ks) * 32 + l], b0, b1);
                    mma16816(e1, sHf[(lt1 * 16 + ks) * 32 + l], b0, b1);
                }
                int ob0 = lt0 * 16, ob1 = lt1 * 16;
                hdro[ra2 * 200 + ob0 + g] = e0[0];     hdro[rb2 * 200 + ob0 + g] = e0[1];
                hdro[ra2 * 200 + ob0 + g + 8] = e0[2]; hdro[rb2 * 200 + ob0 + g + 8] = e0[3];
                hdro[ra2 * 200 + ob1 + g] = e1[0];     hdro[rb2 * 200 + ob1 + g] = e1[1];
                hdro[ra2 * 200 + ob1 + g + 8] = e1[2]; hdro[rb2 * 200 + ob1 + g + 8] = e1[3];
            } else {
                int lt = w;
                float eA[4], eB[4];
                eA[0] = eA[1] = sbh[hb + lt * 16 + g];
                eA[2] = eA[3] = sbh[hb + lt * 16 + g + 8];
                eB[0] = eB[1] = eB[2] = eB[3] = 0.f;
#pragma unroll
                for (int j = 0; j < 8; j++) {
                    int ks = ko + j;
                    u32 b0 = *(const u32*)&zb[g * 264 + ks * 16 + ti * 2];
                    u32 b1 = *(const u32*)&zb[g * 264 + ks * 16 + ti * 2 + 8];
                    mma16816((j & 1) ? eB : eA, sHf[(lt * 16 + ks) * 32 + l], b0, b1);
                }
                mbar_wait(mb_zb, par);
#pragma unroll
                for (int j = 0; j < 8; j++) {
                    int ks = kp + j;
                    u32 b0 = *(const u32*)&zb[g * 264 + ks * 16 + ti * 2];
                    u32 b1 = *(const u32*)&zb[g * 264 + ks * 16 + ti * 2 + 8];
                    mma16816((j & 1) ? eA : eB, sHf[(lt * 16 + ks) * 32 + l], b0, b1);
                }
                int ob = lt * 16;
                hdro[ra2 * 200 + ob + g] = eA[0] + eB[0];
                hdro[rb2 * 200 + ob + g] = eA[1] + eB[1];
                hdro[ra2 * 200 + ob + g + 8] = eA[2] + eB[2];
                hdro[rb2 * 200 + ob + g + 8] = eA[3] + eB[3];
            }
        }
        __syncthreads();   // hdro ready

        // ================= combine + feedback + h store ===================
#pragma unroll
        for (int it = 0; it < 2; it++) {
            int i = t + 256 * it;
            int row = i >> 6, j = i & 63;
            float f1 = tanhf_fast(hdro[row * 200 + j]);
            float f2 = tanhf_fast(hdro[row * 200 + 64 + j]);
            float sg = sigf(hdro[row * 200 + 128 + j]);
            float h = f1 + sg * (f2 - f1);
            int jg = 64 * (int)rank + j;
            __half hh = __float2half(h);
            int idx = row * 168 + 16 + jg;
            in0[idx] = hh;
            sts_r16(in0_r + idx * 2, hh);
            g_hs[((bb + row) * S_ + step) * H_ + jg] = h;
        }
        mbar_arrive_remote(mb_h_r);
        // x(s+1) into local in0 (local-only; peer never reads our x slots)
        if (step + 1 < S_) {
            for (int i = t; i < ROWS * F_; i += 256) {
                int r = i / F_, f = i % F_;
                in0[r * 168 + f] = __float2half(g_x1[((bb + r) * S_ + step + 1) * F_ + f]);
            }
        }
    }
    CLUSTER_SYNC();   // peer may still be writing our smem
}

// ---------------- fused back ----------------
__global__ void k_back(const float* __restrict__ Wfc, const float* __restrict__ bfc,
                       float* __restrict__ out) {
    __shared__ float r1s[S_][4];
    int b = blockIdx.x, t = threadIdx.x;
    int w = t >> 5, lane = t & 31;
    for (int s = w; s < S_; s += 8) {
        const float* h = g_hs + (size_t)(b * S_ + s) * H_;
        float a0 = 0.f, a1 = 0.f, a2 = 0.f;
        for (int i = lane; i < H_; i += 32) {
            float hv = h[i];
            a0 = fmaf(hv, Wfc[i], a0);
            a1 = fmaf(hv, Wfc[H_ + i], a1);
            a2 = fmaf(hv, Wfc[2 * H_ + i], a2);
        }
#pragma unroll
        for (int o = 16; o; o >>= 1) {
            a0 += __shfl_xor_sync(0xffffffffu, a0, o);
            a1 += __shfl_xor_sync(0xffffffffu, a1, o);
            a2 += __shfl_xor_sync(0xffffffffu, a2, o);
        }
        if (!lane) {
            r1s[s][0] = a0 + bfc[0] + g_x3[(b * S_ + s) * 3 + 0];
            r1s[s][1] = a1 + bfc[1] + g_x3[(b * S_ + s) * 3 + 1];
            r1s[s][2] = a2 + bfc[2] + g_x3[(b * S_ + s) * 3 + 2];
        }
    }
    __syncthreads();
    if (t < S_) {
        float a0 = g_mean[b * F_ + 0] + g_x2[(b * S_ + t) * 3 + 0];
        float a1 = g_mean[b * F_ + 1] + g_x2[(b * S_ + t) * 3 + 1];
        float a2 = g_mean[b * F_ + 2] + g_x2[(b * S_ + t) * 3 + 2];
        for (int s = 0; s < S_; ++s) {
            a0 = fmaf(r1s[s][0], g_WfT[0 * S2_ + s * S_ + t], a0);
            a1 = fmaf(r1s[s][1], g_WfT[1 * S2_ + s * S_ + t], a1);
            a2 = fmaf(r1s[s][2], g_WfT[2 * S2_ + s * S_ + t], a2);
        }
        float* o = out + (b * S_ + t) * 3;
        o[0] = a0; o[1] = a1; o[2] = a2;
    }
}

// ---------------- launch ----------------
extern "C" void kernel_launch(void* const* d_in, const int* in_sizes, int n_in,
                              void* d_out, int out_size) {
    const float* x     = (const float*)d_in[0];
    const float* c3    = (const float*)d_in[1];
    const float* l3    = (const float*)d_in[2];
    const float* c6    = (const float*)d_in[3];
    const float* l6    = (const float*)d_in[4];
    const float* c12   = (const float*)d_in[5];
    const float* l12   = (const float*)d_in[6];
    const float* c24   = (const float*)d_in[7];
    const float* l24   = (const float*)d_in[8];
    const float* Wb0   = (const float*)d_in[9];
    const float* bb0   = (const float*)d_in[10];
    const float* Wb1   = (const float*)d_in[11];
    const float* bb1   = (const float*)d_in[12];
    const float* Wff1  = (const float*)d_in[13];
    const float* bff1  = (const float*)d_in[14];
    const float* Wff2  = (const float*)d_in[15];
    const float* bff2  = (const float*)d_in[16];
    const float* Wta   = (const float*)d_in[17];
    const float* bta   = (const float*)d_in[18];
    const float* Wtb   = (const float*)d_in[19];
    const float* btb   = (const float*)d_in[20];
    const float* Wfc   = (const float*)d_in[21];
    const float* bfc   = (const float*)d_in[22];
    const float* Wfits = (const float*)d_in[23];
    float* out = (float*)d_out;

    const int SMEM_RNN = 221856;
    cudaFuncSetAttribute(k_rnn, cudaFuncAttributeMaxDynamicSharedMemorySize, SMEM_RNN);

    const int NPREP = 16 * 9 * 32 + 16 * 16 * 32 + 24 * 16 * 32 + 384;
    k_prep<<<(NPREP + 255) / 256, 256>>>(Wb0, Wb1, Wff1, Wff2, Wta, Wtb,
                                         bff1, bff2, bta, btb);
    k_build_T<<<(3 * S2_ + 255) / 256, 256>>>(c3, l3, c6, l6, c12, l12, c24, l24);
    k_twf<<<(3 * S2_ + 255) / 256, 256>>>(Wfits);
    k_mean<<<(B_ * F_ * 32 + 255) / 256, 256>>>(x);
    k_front<<<B_, 192>>>(x);
    k_rnn<<<128, 256, SMEM_RNN>>>(bb0, bb1);
    k_back<<<B_, 256>>>(Wfc, bfc, out);
}

// round 9
// speedup vs baseline: 1.0328x; 1.0328x over previous
#include <cuda_runtime.h>
#include <cuda_fp16.h>

#define B_ 512
#define S_ 168
#define F_ 12
#define H_ 128
#define O_ 3
#define S2_ (S_ * S_)
#define ROWS 8

typedef unsigned int u32;

// ---------------- device scratch ----------------
__device__ uint4 g_W0f[16 * 9 * 32];    // L0 fragments [tile][kstep][lane]  (K=144: x|pad|h)
__device__ uint4 g_W1f[16 * 16 * 32];   // L1 fragments
__device__ uint4 g_Hf[24 * 16 * 32];    // head fragments (re-ordered blocks)
__device__ float g_bh[384];             // merged head bias (re-ordered)
__device__ float g_T[3 * S2_];          // transposed [L][si][so]
__device__ float g_WfT[3 * S2_];        // transposed [c][s][p]
__device__ float g_mean[B_ * F_];
__device__ float g_x1[B_ * S_ * F_];
__device__ float g_x2[B_ * S_ * O_];
__device__ float g_x3[B_ * S_ * O_];
__device__ float g_hs[B_ * S_ * H_];

// ---------------- helpers ----------------
__device__ __forceinline__ float tanh_ap(float x) {
    float y;
    asm("tanh.approx.f32 %0, %1;" : "=f"(y) : "f"(x));
    return y;
}
__device__ __forceinline__ float siluf(float x) {
    return x * fmaf(0.5f, tanh_ap(0.5f * x), 0.5f);
}
__device__ __forceinline__ float sigf(float x) {
    return fmaf(0.5f, tanh_ap(0.5f * x), 0.5f);
}
__device__ __forceinline__ u32 hpack(float a, float b) {
    __half2 h = __floats2half2_rn(a, b);
    return *reinterpret_cast<u32*>(&h);
}
__device__ __forceinline__ void mma16816(float* d, uint4 A, u32 b0, u32 b1) {
    asm volatile(
        "mma.sync.aligned.m16n8k16.row.col.f32.f16.f16.f32 "
        "{%0,%1,%2,%3},{%4,%5,%6,%7},{%8,%9},{%0,%1,%2,%3};"
        : "+f"(d[0]), "+f"(d[1]), "+f"(d[2]), "+f"(d[3])
        : "r"(A.x), "r"(A.y), "r"(A.z), "r"(A.w), "r"(b0), "r"(b1));
}
#define CLUSTER_SYNC() do { \
    asm volatile("barrier.cluster.arrive.aligned;" ::: "memory"); \
    asm volatile("barrier.cluster.wait.aligned;" ::: "memory"); } while (0)
#define CLUSTER_ARRIVE() asm volatile("barrier.cluster.arrive.aligned;" ::: "memory")
#define CLUSTER_WAIT()   asm volatile("barrier.cluster.wait.aligned;" ::: "memory")

__device__ __forceinline__ void sts_r16(u32 a, __half v) {
    asm volatile("st.shared::cluster.b16 [%0], %1;" :: "r"(a), "h"(__half_as_ushort(v)));
}

// weight element accessors
// L0 K layout: k in [0,12) -> x, [12,16) -> zero pad, [16,144) -> h[k-16]
__device__ __forceinline__ float w0_at(const float* W, int o, int k) {
    if (k < 12)  return W[o * 140 + k];
    if (k < 16)  return 0.f;
    return W[o * 140 + (k - 4)];     // 12 + (k-16)
}
// head ordering: block r (192 rows) = [ff1(64r:64r+64); ff2(64r:64r+64); gate(64r:64r+64)]
__device__ __forceinline__ float wh_at(const float* f1, const float* f2,
                                       const float* ta, const float* tb, int m, int k) {
    int blk = m / 192, o = m % 192, base = blk * 64;
    if (o < 64)  return f1[(base + o) * 256 + k];
    if (o < 128) return f2[(base + o - 64) * 256 + k];
    return ta[(base + o - 128) * 256 + k] + tb[(base + o - 128) * 256 + k];
}

// ---------------- fragment precompute ----------------
__global__ void k_prep(const float* __restrict__ Wb0, const float* __restrict__ Wb1,
                       const float* __restrict__ Wff1, const float* __restrict__ Wff2,
                       const float* __restrict__ Wta, const float* __restrict__ Wtb,
                       const float* __restrict__ bff1, const float* __restrict__ bff2,
                       const float* __restrict__ bta, const float* __restrict__ btb) {
    int idx = blockIdx.x * blockDim.x + threadIdx.x;
    const int N0 = 16 * 9 * 32, N1 = 16 * 16 * 32, NH = 24 * 16 * 32;
    if (idx < N0 + N1 + NH) {
        int which, tile, ks, l, i = idx;
        if (i < N0)           { which = 0; tile = i / (9 * 32);  ks = (i / 32) % 9; }
        else if (i < N0 + N1) { which = 1; i -= N0; tile = i / (16 * 32); ks = (i / 32) % 16; }
        else                  { which = 2; i -= N0 + N1; tile = i / (16 * 32); ks = (i / 32) % 16; }
        l = i % 32;
        int g = l / 4, ti = l % 4;
        int r0 = tile * 16 + g, k0 = ks * 16 + ti * 2;
        float e[4][2];
        for (int half = 0; half < 2; half++) {
            for (int rr = 0; rr < 2; rr++) {
                for (int cc = 0; cc < 2; cc++) {
                    int o = r0 + rr * 8, k = k0 + half * 8 + cc;
                    float wv;
                    if (which == 0)      wv = w0_at(Wb0, o, k);
                    else if (which == 1) wv = Wb1[o * 256 + k];
                    else                 wv = wh_at(Wff1, Wff2, Wta, Wtb, o, k);
                    e[half * 2 + rr][cc] = wv;
                }
            }
        }
        uint4 out;
        out.x = hpack(e[0][0], e[0][1]);
        out.y = hpack(e[1][0], e[1][1]);
        out.z = hpack(e[2][0], e[2][1]);
        out.w = hpack(e[3][0], e[3][1]);
        if (which == 0)      g_W0f[idx] = out;
        else if (which == 1) g_W1f[idx - N0] = out;
        else                 g_Hf[idx - N0 - N1] = out;
    } else if (idx < N0 + N1 + NH + 384) {
        int m = idx - N0 - N1 - NH;
        int blk = m / 192, o = m % 192, base = blk * 64;
        float b;
        if (o < 64)       b = bff1[base + o];
        else if (o < 128) b = bff2[base + o - 64];
        else              b = bta[base + o - 128] + btb[base + o - 128];
        g_bh[m] = b;
    }
}

// ---------------- collapsed _sff operators (transposed) ----------------
__device__ __forceinline__ float sff_contrib(const float* __restrict__ conv,
                                             const float* __restrict__ lin,
                                             int p, int seg, int pad, int so, int si) {
    int phase = so % p, q = so / p;
    float acc = 0.f;
    for (int kk = 0; kk < seg; ++kk) {
        int d = si - (kk * p + phase);
        float c = 0.f;
        if (d >= -pad && d <= pad) c = conv[d + pad];
        if (d == 0) c += 1.f;
        acc += lin[q * seg + kk] * c;
    }
    return acc;
}

__global__ void k_build_T(const float* __restrict__ c3, const float* __restrict__ l3,
                          const float* __restrict__ c6, const float* __restrict__ l6,
                          const float* __restrict__ c12, const float* __restrict__ l12,
                          const float* __restrict__ c24, const float* __restrict__ l24) {
    int idx = blockIdx.x * blockDim.x + threadIdx.x;
    if (idx >= 3 * S2_) return;
    int L = idx / S2_, r = idx % S2_;
    int so = r / S_, si = r % S_;
    float a = sff_contrib(c3 + L * 3, l3 + L * 56 * 56, 3, 56, 1, so, si)
            + sff_contrib(c6 + L * 7, l6 + L * 28 * 28, 6, 28, 3, so, si)
            + sff_contrib(c12 + L * 13, l12 + L * 14 * 14, 12, 14, 6, so, si)
            + sff_contrib(c24 + L * 25, l24 + L * 7 * 7, 24, 7, 12, so, si);
    g_T[L * S2_ + si * S_ + so] = 0.25f * a;
}

__global__ void k_twf(const float* __restrict__ Wfits) {
    int idx = blockIdx.x * blockDim.x + threadIdx.x;
    if (idx >= 3 * S2_) return;
    int c = idx / S2_, r = idx % S2_;
    int s = r / S_, p = r % S_;
    g_WfT[c * S2_ + s * S_ + p] = Wfits[c * S2_ + p * S_ + s];
}

__global__ void k_mean(const float* __restrict__ x) {
    int w = (blockIdx.x * blockDim.x + threadIdx.x) >> 5;
    int lane = threadIdx.x & 31;
    if (w >= B_ * F_) return;
    const float* p = x + w * S_;
    float s = 0.f;
    for (int i = lane; i < S_; i += 32) s += p[i];
#pragma unroll
    for (int o = 16; o; o >>= 1) s += __shfl_xor_sync(0xffffffffu, s, o);
    if (!lane) g_mean[w] = s * (1.f / (float)S_);
}

// ---------------- fused front ----------------
__global__ void k_front(const float* __restrict__ x) {
    __shared__ float xs[S_][F_];
    __shared__ float x1s[S_][4];
    int b = blockIdx.x, t = threadIdx.x;
    for (int i = t; i < S_ * F_; i += blockDim.x) {
        int si = i / F_, f = i % F_;
        xs[si][f] = x[b * F_ * S_ + f * S_ + si] - g_mean[b * F_ + f];
    }
    __syncthreads();
    if (t < S_) {
        float acc[F_];
#pragma unroll
        for (int f = 0; f < F_; f++) acc[f] = 0.f;
        for (int si = 0; si < S_; ++si) {
            float tw = g_T[si * S_ + t];
#pragma unroll
            for (int f = 0; f < F_; f++) acc[f] = fmaf(tw, xs[si][f], acc[f]);
        }
        float* o = g_x1 + (b * S_ + t) * F_;
#pragma unroll
        for (int f = 0; f < F_; f++) o[f] = acc[f];
        x1s[t][0] = acc[0]; x1s[t][1] = acc[1]; x1s[t][2] = acc[2];
    }
    __syncthreads();
    if (t < S_) {
        float a2[3] = {0.f, 0.f, 0.f}, a3[3] = {0.f, 0.f, 0.f};
        for (int si = 0; si < S_; ++si) {
            float t1 = g_T[S2_ + si * S_ + t];
            float t2 = g_T[2 * S2_ + si * S_ + t];
#pragma unroll
            for (int c = 0; c < 3; c++) {
                a2[c] = fmaf(t1, x1s[si][c], a2[c]);
                a3[c] = fmaf(t2, x1s[si][c], a3[c]);
            }
        }
#pragma unroll
        for (int c = 0; c < 3; c++) {
            g_x2[(b * S_ + t) * 3 + c] = a2[c];
            g_x3[(b * S_ + t) * 3 + c] = a3[c];
        }
    }
}

// ---------------- CfC recurrence: cluster-2, split arrive/wait ----------
// SMEM layout (bytes):
//   [0, 36864)        sW0   (8 tiles x 9 ks x 32 x uint4)
//   [36864, 102400)   sW1   (8 x 16 x 32)
//   [102400, 200704)  sHf   (12 x 16 x 32)
//   [200704, 203392)  in0   8 rows x 168 halfs  ([x12|pad4|h128])
//   [203392, 207616)  za    8 x 264 halfs
//   [207616, 211840)  zb    8 x 264 halfs
//   [211840, 218240)  hdro  8 x 200 floats
//   [218240, 219264)  sb0
//   [219264, 220288)  sb1
//   [220288, 221824)  sbh
__global__ void __launch_bounds__(256, 1) __cluster_dims__(2, 1, 1)
k_rnn(const float* __restrict__ bb0, const float* __restrict__ bb1) {
    extern __shared__ __align__(16) char s[];
    uint4*  sW0  = (uint4*)(s);
    uint4*  sW1  = (uint4*)(s + 36864);
    uint4*  sHf  = (uint4*)(s + 102400);
    __half* in0  = (__half*)(s + 200704);
    __half* za   = (__half*)(s + 203392);
    __half* zb   = (__half*)(s + 207616);
    float*  hdro = (float*)(s + 211840);
    float*  sb0  = (float*)(s + 218240);
    float*  sb1  = (float*)(s + 219264);
    float*  sbh  = (float*)(s + 220288);

    const int t = threadIdx.x, w = t >> 5, l = t & 31, g = l >> 2, ti = l & 3;
    u32 rank;
    asm("mov.u32 %0, %%cluster_ctarank;" : "=r"(rank));
    const u32 peer = rank ^ 1u;
    const int bb = (blockIdx.x >> 1) * ROWS;

    u32 base;
    asm("{ .reg .u64 a; cvta.to.shared.u64 a, %1; cvt.u32.u64 %0, a; }" : "=r"(base) : "l"(s));
    u32 in0_l = base + 200704, za_l = base + 203392, zb_l = base + 207616;
    u32 in0_r, za_r, zb_r;
    asm("mapa.shared::cluster.u32 %0, %1, %2;" : "=r"(in0_r) : "r"(in0_l), "r"(peer));
    asm("mapa.shared::cluster.u32 %0, %1, %2;" : "=r"(za_r) : "r"(za_l), "r"(peer));
    asm("mapa.shared::cluster.u32 %0, %1, %2;" : "=r"(zb_r) : "r"(zb_l), "r"(peer));

    // stage this CTA's half of each weight matrix + biases
    {
        const uint4* p0 = g_W0f + rank * 2304;
        for (int i = t; i < 2304; i += 256) sW0[i] = p0[i];
        const uint4* p1 = g_W1f + rank * 4096;
        for (int i = t; i < 4096; i += 256) sW1[i] = p1[i];
        const uint4* ph = g_Hf + rank * 6144;
        for (int i = t; i < 6144; i += 256) sHf[i] = ph[i];
    }
    sb0[t] = bb0[t];
    sb1[t] = bb1[t];
    for (int i = t; i < 384; i += 256) sbh[i] = g_bh[i];
    for (int i = t; i < ROWS * 168; i += 256) in0[i] = __float2half(0.f);
    __syncthreads();
    CLUSTER_SYNC();        // zeroed in0 (h part) visible cluster-wide
    CLUSTER_ARRIVE();      // seed h-phase for step 0
    // load x(0) (local only)
    for (int i = t; i < ROWS * F_; i += 256) {
        int r = i / F_, f = i % F_;
        in0[r * 168 + f] = __float2half(g_x1[(bb + r) * S_ * F_ + f]);
    }

    const int ra2 = 2 * ti, rb2 = 2 * ti + 1;
    const int hb = 192 * (int)rank;
    const int gob = (8 * (int)rank + w) * 16;   // L0/L1 global out base
    const int ko1 = 1 + 4 * (int)rank, kp1 = 1 + 4 * (int)peer;   // L0 h ks
    const int ko = 8 * (int)rank, kp = 8 * (int)peer;             // L1/head ks

    for (int step = 0; step < S_; ++step) {
        __syncthreads();   // local in0 writes (x(s), own h(s-1)) visible

        // ================= L0 (K=144: ks0=x, own h, [wait], peer h) =======
        float dA[4], dB[4];
        {
            dA[0] = dA[1] = sb0[gob + g];
            dA[2] = dA[3] = sb0[gob + g + 8];
            dB[0] = dB[1] = dB[2] = dB[3] = 0.f;
            {
                u32 b0 = *(const u32*)&in0[g * 168 + ti * 2];
                u32 b1 = *(const u32*)&in0[g * 168 + ti * 2 + 8];
                mma16816(dA, sW0[(w * 9 + 0) * 32 + l], b0, b1);
            }
#pragma unroll
            for (int j = 0; j < 4; j++) {
                int ks = ko1 + j;
                u32 b0 = *(const u32*)&in0[g * 168 + ks * 16 + ti * 2];
                u32 b1 = *(const u32*)&in0[g * 168 + ks * 16 + ti * 2 + 8];
                mma16816((j & 1) ? dB : dA, sW0[(w * 9 + ks) * 32 + l], b0, b1);
            }
        }
        CLUSTER_WAIT();    // h(s-1) peer half landed
        {
#pragma unroll
            for (int j = 0; j < 4; j++) {
                int ks = kp1 + j;
                u32 b0 = *(const u32*)&in0[g * 168 + ks * 16 + ti * 2];
                u32 b1 = *(const u32*)&in0[g * 168 + ks * 16 + ti * 2 + 8];
                mma16816((j & 1) ? dA : dB, sW0[(w * 9 + ks) * 32 + l], b0, b1);
            }
            float v0 = siluf(dA[0] + dB[0]), v1 = siluf(dA[1] + dB[1]);
            float v2 = siluf(dA[2] + dB[2]), v3 = siluf(dA[3] + dB[3]);
            __half h0 = __float2half(v0), h1 = __float2half(v1);
            __half h2 = __float2half(v2), h3 = __float2half(v3);
            int i0 = ra2 * 264 + gob + g, i1 = rb2 * 264 + gob + g;
            za[i0] = h0;     za[i1] = h1;
            za[i0 + 8] = h2; za[i1 + 8] = h3;
            sts_r16(za_r + i0 * 2, h0);       sts_r16(za_r + i1 * 2, h1);
            sts_r16(za_r + (i0 + 8) * 2, h2); sts_r16(za_r + (i1 + 8) * 2, h3);
        }
        CLUSTER_ARRIVE();  // za phase (release: our remote za stores)
        __syncthreads();   // local za half visible

        // ================= L1 (own za ks, [wait], peer za ks) =============
        {
            dA[0] = dA[1] = sb1[gob + g];
            dA[2] = dA[3] = sb1[gob + g + 8];
            dB[0] = dB[1] = dB[2] = dB[3] = 0.f;
#pragma unroll
            for (int j = 0; j < 8; j++) {
                int ks = ko + j;
                u32 b0 = *(const u32*)&za[g * 264 + ks * 16 + ti * 2];
                u32 b1 = *(const u32*)&za[g * 264 + ks * 16 + ti * 2 + 8];
                mma16816((j & 1) ? dB : dA, sW1[(w * 16 + ks) * 32 + l], b0, b1);
            }
        }
        CLUSTER_WAIT();    // peer za landed
        {
#pragma unroll
            for (int j = 0; j < 8; j++) {
                int ks = kp + j;
                u32 b0 = *(const u32*)&za[g * 264 + ks * 16 + ti * 2];
                u32 b1 = *(const u32*)&za[g * 264 + ks * 16 + ti * 2 + 8];
                mma16816((j & 1) ? dA : dB, sW1[(w * 16 + ks) * 32 + l], b0, b1);
            }
            float v0 = siluf(dA[0] + dB[0]), v1 = siluf(dA[1] + dB[1]);
            float v2 = siluf(dA[2] + dB[2]), v3 = siluf(dA[3] + dB[3]);
            __half h0 = __float2half(v0), h1 = __float2half(v1);
            __half h2 = __float2half(v2), h3 = __float2half(v3);
            int i0 = ra2 * 264 + gob + g, i1 = rb2 * 264 + gob + g;
            zb[i0] = h0;     zb[i1] = h1;
            zb[i0 + 8] = h2; zb[i1 + 8] = h3;
            sts_r16(zb_r + i0 * 2, h0);       sts_r16(zb_r + i1 * 2, h1);
            sts_r16(zb_r + (i0 + 8) * 2, h2); sts_r16(zb_r + (i1 + 8) * 2, h3);
        }
        CLUSTER_ARRIVE();  // zb phase
        __syncthreads();   // local zb visible

        // ================= head (own ks, [wait], peer ks) =================
        {
            const bool two = (w < 4);
            const int lt0 = w, lt1 = 8 + w;   // lt1 used only when two
            float e0[4], e1[4];
            e0[0] = e0[1] = sbh[hb + lt0 * 16 + g];
            e0[2] = e0[3] = sbh[hb + lt0 * 16 + g + 8];
            if (two) {
                e1[0] = e1[1] = sbh[hb + lt1 * 16 + g];
                e1[2] = e1[3] = sbh[hb + lt1 * 16 + g + 8];
            } else {
                e1[0] = e1[1] = e1[2] = e1[3] = 0.f;
            }
#pragma unroll
            for (int j = 0; j < 8; j++) {
                int ks = ko + j;
                u32 b0 = *(const u32*)&zb[g * 264 + ks * 16 + ti * 2];
                u32 b1 = *(const u32*)&zb[g * 264 + ks * 16 + ti * 2 + 8];
                if (two) {
                    mma16816(e0, sHf[(lt0 * 16 + ks) * 32 + l], b0, b1);
                    mma16816(e1, sHf[(lt1 * 16 + ks) * 32 + l], b0, b1);
                } else {
                    mma16816((j & 1) ? e1 : e0, sHf[(lt0 * 16 + ks) * 32 + l], b0, b1);
                }
            }
            CLUSTER_WAIT();   // peer zb landed (convergent: all warps reach this)
#pragma unroll
            for (int j = 0; j < 8; j++) {
                int ks = kp + j;
                u32 b0 = *(const u32*)&zb[g * 264 + ks * 16 + ti * 2];
                u32 b1 = *(const u32*)&zb[g * 264 + ks * 16 + ti * 2 + 8];
                if (two) {
                    mma16816(e0, sHf[(lt0 * 16 + ks) * 32 + l], b0, b1);
                    mma16816(e1, sHf[(lt1 * 16 + ks) * 32 + l], b0, b1);
                } else {
                    mma16816((j & 1) ? e0 : e1, sHf[(lt0 * 16 + ks) * 32 + l], b0, b1);
                }
            }
            if (two) {
                int ob0 = lt0 * 16, ob1 = lt1 * 16;
                hdro[ra2 * 200 + ob0 + g] = e0[0];     hdro[rb2 * 200 + ob0 + g] = e0[1];
                hdro[ra2 * 200 + ob0 + g + 8] = e0[2]; hdro[rb2 * 200 + ob0 + g + 8] = e0[3];
                hdro[ra2 * 200 + ob1 + g] = e1[0];     hdro[rb2 * 200 + ob1 + g] = e1[1];
                hdro[ra2 * 200 + ob1 + g + 8] = e1[2]; hdro[rb2 * 200 + ob1 + g + 8] = e1[3];
            } else {
                int ob = lt0 * 16;
                hdro[ra2 * 200 + ob + g] = e0[0] + e1[0];
                hdro[rb2 * 200 + ob + g] = e0[1] + e1[1];
                hdro[ra2 * 200 + ob + g + 8] = e0[2] + e1[2];
                hdro[rb2 * 200 + ob + g + 8] = e0[3] + e1[3];
            }
        }
        __syncthreads();   // hdro ready

        // ================= combine + feedback + h store ===================
#pragma unroll
        for (int it = 0; it < 2; it++) {
            int i = t + 256 * it;
            int row = i >> 6, j = i & 63;
            float f1 = tanh_ap(hdro[row * 200 + j]);
            float f2 = tanh_ap(hdro[row * 200 + 64 + j]);
            float sg = sigf(hdro[row * 200 + 128 + j]);
            float h = f1 + sg * (f2 - f1);
            int jg = 64 * (int)rank + j;
            __half hh = __float2half(h);
            int idx = row * 168 + 16 + jg;
            in0[idx] = hh;
            sts_r16(in0_r + idx * 2, hh);
            g_hs[((bb + row) * S_ + step) * H_ + jg] = h;
        }
        if (step + 1 < S_) {
            CLUSTER_ARRIVE();   // h phase for next step
            for (int i = t; i < ROWS * F_; i += 256) {
                int r = i / F_, f = i % F_;
                in0[r * 168 + f] = __float2half(g_x1[((bb + r) * S_ + step + 1) * F_ + f]);
            }
        }
    }
    CLUSTER_SYNC();   // drain: peer may still be writing our smem
}

// ---------------- fused back ----------------
__global__ void k_back(const float* __restrict__ Wfc, const float* __restrict__ bfc,
                       float* __restrict__ out) {
    __shared__ float r1s[S_][4];
    int b = blockIdx.x, t = threadIdx.x;
    int w = t >> 5, lane = t & 31;
    for (int s = w; s < S_; s += 8) {
        const float* h = g_hs + (size_t)(b * S_ + s) * H_;
        float a0 = 0.f, a1 = 0.f, a2 = 0.f;
        for (int i = lane; i < H_; i += 32) {
            float hv = h[i];
            a0 = fmaf(hv, Wfc[i], a0);
            a1 = fmaf(hv, Wfc[H_ + i], a1);
            a2 = fmaf(hv, Wfc[2 * H_ + i], a2);
        }
#pragma unroll
        for (int o = 16; o; o >>= 1) {
            a0 += __shfl_xor_sync(0xffffffffu, a0, o);
            a1 += __shfl_xor_sync(0xffffffffu, a1, o);
            a2 += __shfl_xor_sync(0xffffffffu, a2, o);
        }
        if (!lane) {
            r1s[s][0] = a0 + bfc[0] + g_x3[(b * S_ + s) * 3 + 0];
            r1s[s][1] = a1 + bfc[1] + g_x3[(b * S_ + s) * 3 + 1];
            r1s[s][2] = a2 + bfc[2] + g_x3[(b * S_ + s) * 3 + 2];
        }
    }
    __syncthreads();
    if (t < S_) {
        float a0 = g_mean[b * F_ + 0] + g_x2[(b * S_ + t) * 3 + 0];
        float a1 = g_mean[b * F_ + 1] + g_x2[(b * S_ + t) * 3 + 1];
        float a2 = g_mean[b * F_ + 2] + g_x2[(b * S_ + t) * 3 + 2];
        for (int s = 0; s < S_; ++s) {
            a0 = fmaf(r1s[s][0], g_WfT[0 * S2_ + s * S_ + t], a0);
            a1 = fmaf(r1s[s][1], g_WfT[1 * S2_ + s * S_ + t], a1);
            a2 = fmaf(r1s[s][2], g_WfT[2 * S2_ + s * S_ + t], a2);
        }
        float* o = out + (b * S_ + t) * 3;
        o[0] = a0; o[1] = a1; o[2] = a2;
    }
}

// ---------------- launch ----------------
extern "C" void kernel_launch(void* const* d_in, const int* in_sizes, int n_in,
                              void* d_out, int out_size) {
    const float* x     = (const float*)d_in[0];
    const float* c3    = (const float*)d_in[1];
    const float* l3    = (const float*)d_in[2];
    const float* c6    = (const float*)d_in[3];
    const float* l6    = (const float*)d_in[4];
    const float* c12   = (const float*)d_in[5];
    const float* l12   = (const float*)d_in[6];
    const float* c24   = (const float*)d_in[7];
    const float* l24   = (const float*)d_in[8];
    const float* Wb0   = (const float*)d_in[9];
    const float* bb0   = (const float*)d_in[10];
    const float* Wb1   = (const float*)d_in[11];
    const float* bb1   = (const float*)d_in[12];
    const float* Wff1  = (const float*)d_in[13];
    const float* bff1  = (const float*)d_in[14];
    const float* Wff2  = (const float*)d_in[15];
    const float* bff2  = (const float*)d_in[16];
    const float* Wta   = (const float*)d_in[17];
    const float* bta   = (const float*)d_in[18];
    const float* Wtb   = (const float*)d_in[19];
    const float* btb   = (const float*)d_in[20];
    const float* Wfc   = (const float*)d_in[21];
    const float* bfc   = (const float*)d_in[22];
    const float* Wfits = (const float*)d_in[23];
    float* out = (float*)d_out;

    const int SMEM_RNN = 221824;
    cudaFuncSetAttribute(k_rnn, cudaFuncAttributeMaxDynamicSharedMemorySize, SMEM_RNN);

    const int NPREP = 16 * 9 * 32 + 16 * 16 * 32 + 24 * 16 * 32 + 384;
    k_prep<<<(NPREP + 255) / 256, 256>>>(Wb0, Wb1, Wff1, Wff2, Wta, Wtb,
                                         bff1, bff2, bta, btb);
    k_build_T<<<(3 * S2_ + 255) / 256, 256>>>(c3, l3, c6, l6, c12, l12, c24, l24);
    k_twf<<<(3 * S2_ + 255) / 256, 256>>>(Wfits);
    k_mean<<<(B_ * F_ * 32 + 255) / 256, 256>>>(x);
    k_front<<<B_, 192>>>(x);
    k_rnn<<<128, 256, SMEM_RNN>>>(bb0, bb1);
    k_back<<<B_, 256>>>(Wfc, bfc, out);
}